// round 7
// baseline (speedup 1.0000x reference)
#include <cuda_runtime.h>

// BilinearInteractionLayer: out[b, p, e] = (x[b,i(p)] @ W)[e] * x[b,j(p)][e]
// B=8192, F=32, E=64, P=496. Pure HBM-store-bound (~1.047 GB out, traffic-minimal).
//
// R7 design: one CTA/batch row, 256 threads.
//   - Only xs (8 KB) in smem -> 8 CTAs/SM (warp-limited, 100% theoretical occ).
//   - Thread (q = tid&15, w = tid>>4) computes xw rows {w, 30-w} (cols 4q..4q+3)
//     directly INTO REGISTERS (row 31 is never a left row, rows 0..30 suffice),
//     then stores its two runs immediately: NO xws smem, NO second __syncthreads,
//     warps flow GEMM->store independently (smooth store stream).
//   - W read via __ldg from global: 16 KB, L1-resident, broadcast across CTAs.

constexpr int F = 32;
constexpr int E = 64;
constexpr int P = 496;
constexpr int THREADS = 256;

__global__ __launch_bounds__(THREADS) void bilinear_kernel(
    const float* __restrict__ x,     // [B, F, E]
    const float* __restrict__ W,     // [E, E]
    float* __restrict__ out)         // [B, P, E]
{
    __shared__ float xs[F * E];      // 8 KB raw x[b]

    const int tid = threadIdx.x;
    const int b   = blockIdx.x;

    // ---- Stage x[b] into smem (2 x float4 per thread, coalesced) ----
    {
        const float4* xg  = reinterpret_cast<const float4*>(x + (size_t)b * F * E);
        float4*       xs4 = reinterpret_cast<float4*>(xs);
        #pragma unroll
        for (int i = 0; i < (F * E / 4) / THREADS; i++)       // 2 iters
            xs4[tid + i * THREADS] = xg[tid + i * THREADS];
    }
    __syncthreads();                 // the ONLY barrier

    const int q  = tid & 15;         // column group (4 floats)
    const int w  = tid >> 4;         // 0..15
    const int i1 = w;                // run 1 left row
    const int i2 = 30 - w;           // run 2 left row (== i1 when w==15)

    // ---- GEMM into registers: acc0 = xw[i1], acc1 = xw[i2] (cols 4q..4q+3) ----
    float4 acc0 = {0.f,0.f,0.f,0.f};
    float4 acc1 = {0.f,0.f,0.f,0.f};
    {
        const float4* Wv = reinterpret_cast<const float4*>(W);
        #pragma unroll 8
        for (int k = 0; k < E; k++) {
            const float4 wv = __ldg(&Wv[k * 16 + q]);
            const float  a0 = xs[i1 * E + k];
            const float  a1 = xs[i2 * E + k];
            acc0.x += a0*wv.x; acc0.y += a0*wv.y; acc0.z += a0*wv.z; acc0.w += a0*wv.w;
            acc1.x += a1*wv.x; acc1.y += a1*wv.y; acc1.z += a1*wv.z; acc1.w += a1*wv.w;
        }
    }

    // ---- Store: run i covers pairs (i, j=i+1..31); p0(i) = 31i - i(i-1)/2. ----
    // Per output float4: 1 LDS.128 (c) + 1 STG.128. a held in registers.
    {
        const float4* xv = reinterpret_cast<const float4*>(xs);
        float4* og = reinterpret_cast<float4*>(out + (size_t)b * P * E) + q;

        // Run 1: i = i1, length 31 - i1
        {
            float4* dst = og + (size_t)(i1 * 31 - i1 * (i1 - 1) / 2) * 16;
            #pragma unroll 4
            for (int j = i1 + 1; j < F; j++, dst += 16) {
                const float4 c = xv[j * 16 + q];
                float4 r;
                r.x = acc0.x*c.x; r.y = acc0.y*c.y;
                r.z = acc0.z*c.z; r.w = acc0.w*c.w;
                *dst = r;
            }
        }
        // Run 2: i = i2 = 30 - w, length w + 1; skip for w == 15 (duplicate)
        if (w < 15) {
            float4* dst = og + (size_t)(i2 * 31 - i2 * (i2 - 1) / 2) * 16;
            #pragma unroll 4
            for (int j = i2 + 1; j < F; j++, dst += 16) {
                const float4 c = xv[j * 16 + q];
                float4 r;
                r.x = acc1.x*c.x; r.y = acc1.y*c.y;
                r.z = acc1.z*c.z; r.w = acc1.w*c.w;
                *dst = r;
            }
        }
    }
}

extern "C" void kernel_launch(void* const* d_in, const int* in_sizes, int n_in,
                              void* d_out, int out_size)
{
    // Robust input-order detection: W has exactly E*E elements, x is much larger.
    const float* x;
    const float* W;
    int x_elems;
    if (n_in >= 2 && in_sizes[0] > in_sizes[1]) {
        x = (const float*)d_in[0]; W = (const float*)d_in[1]; x_elems = in_sizes[0];
    } else {
        x = (const float*)d_in[1]; W = (const float*)d_in[0]; x_elems = in_sizes[1];
    }

    float* out = (float*)d_out;               // [B, P, E]
    const int B = x_elems / (F * E);          // 8192
    bilinear_kernel<<<B, THREADS>>>(x, W, out);
}

// round 9
// speedup vs baseline: 1.0628x; 1.0628x over previous
#include <cuda_runtime.h>

// BilinearInteractionLayer: out[b, p, e] = (x[b,i(p)] @ W)[e] * x[b,j(p)][e]
// B=8192, F=32, E=64, P=496. HBM-store-bound (~1.047 GB out, traffic-minimal).
//
// R8 = R6 (best: staged-W smem GEMM, run-structured store) plus:
//   - xs GEMM loads vectorized to float4 (4x fewer LDS instr in GEMM)
//   - Ws/xws share one smem buffer (W dead after GEMM; xw born after)
//     -> smem 33KB -> 24.5KB -> 8 CTAs/SM (warp-limited) instead of 6

constexpr int F = 32;
constexpr int E = 64;
constexpr int P = 496;
constexpr int THREADS = 256;

__global__ __launch_bounds__(THREADS) void bilinear_kernel(
    const float* __restrict__ x,     // [B, F, E]
    const float* __restrict__ W,     // [E, E]
    float* __restrict__ out)         // [B, P, E]
{
    __shared__ float xs [F * E];     // 8 KB   raw x[b]
    __shared__ float uni[E * E];     // 16 KB  W during GEMM, then xw (first 8 KB)

    const int tid = threadIdx.x;
    const int b   = blockIdx.x;

    // ---- Stage x[b] and W into smem (vectorized, coalesced) ----
    {
        const float4* xg  = reinterpret_cast<const float4*>(x + (size_t)b * F * E);
        float4*       xs4 = reinterpret_cast<float4*>(xs);
        #pragma unroll
        for (int i = 0; i < (F * E / 4) / THREADS; i++)       // 2 iters
            xs4[tid + i * THREADS] = xg[tid + i * THREADS];

        const float4* wg  = reinterpret_cast<const float4*>(W);
        float4*       un4 = reinterpret_cast<float4*>(uni);
        #pragma unroll
        for (int i = 0; i < (E * E / 4) / THREADS; i++)       // 4 iters
            un4[tid + i * THREADS] = wg[tid + i * THREADS];
    }
    __syncthreads();

    // ---- GEMM: xw = xs @ W. 128 threads, 4 rows x 4 cols each, accs in regs. ----
    // Thread (q = t&15, w = t>>4): rows {w, w+8, w+16, w+24}, cols 4q..4q+3.
    float4 acc0 = {0.f,0.f,0.f,0.f};
    float4 acc1 = {0.f,0.f,0.f,0.f};
    float4 acc2 = {0.f,0.f,0.f,0.f};
    float4 acc3 = {0.f,0.f,0.f,0.f};
    const int q = tid & 15;
    const int w = tid >> 4;
    if (tid < 128) {
        const float4* Wv  = reinterpret_cast<const float4*>(uni);
        const float4* xsv = reinterpret_cast<const float4*>(xs);
        #pragma unroll
        for (int k4 = 0; k4 < E / 4; k4++) {
            // Vectorized xs row loads: one float4 per row per 4 k-steps
            const float4 a0v = xsv[(w     ) * 16 + k4];
            const float4 a1v = xsv[(w +  8) * 16 + k4];
            const float4 a2v = xsv[(w + 16) * 16 + k4];
            const float4 a3v = xsv[(w + 24) * 16 + k4];
            const float* a0p = &a0v.x;
            const float* a1p = &a1v.x;
            const float* a2p = &a2v.x;
            const float* a3p = &a3v.x;
            #pragma unroll
            for (int kk = 0; kk < 4; kk++) {
                const float4 wv = Wv[(k4 * 4 + kk) * 16 + q];
                const float a0 = a0p[kk], a1 = a1p[kk], a2 = a2p[kk], a3 = a3p[kk];
                acc0.x += a0*wv.x; acc0.y += a0*wv.y; acc0.z += a0*wv.z; acc0.w += a0*wv.w;
                acc1.x += a1*wv.x; acc1.y += a1*wv.y; acc1.z += a1*wv.z; acc1.w += a1*wv.w;
                acc2.x += a2*wv.x; acc2.y += a2*wv.y; acc2.z += a2*wv.z; acc2.w += a2*wv.w;
                acc3.x += a3*wv.x; acc3.y += a3*wv.y; acc3.z += a3*wv.z; acc3.w += a3*wv.w;
            }
        }
    }
    __syncthreads();                 // all W reads done; uni may be overwritten

    if (tid < 128) {
        float4* xwv = reinterpret_cast<float4*>(uni);     // overlay: xw in uni
        xwv[(w     ) * 16 + q] = acc0;
        xwv[(w +  8) * 16 + q] = acc1;
        xwv[(w + 16) * 16 + q] = acc2;
        xwv[(w + 24) * 16 + q] = acc3;
    }
    __syncthreads();

    // ---- Store: worker w2 owns runs i=w2 and i=30-w2; p0(i) = 31i - i(i-1)/2. ----
    // a = xw[i] register-cached per run; per row: 1 LDS.128 + 1 STG.128.
    {
        const int w2 = tid >> 4;         // 0..15
        const float4* xwv = reinterpret_cast<const float4*>(uni);
        const float4* xv  = reinterpret_cast<const float4*>(xs);
        float4* og = reinterpret_cast<float4*>(out + (size_t)b * P * E) + q;

        // Run 1: i = w2 (length 31 - w2)
        {
            const int i = w2;
            const float4 a = xwv[i * 16 + q];
            float4* dst = og + (size_t)(i * 31 - i * (i - 1) / 2) * 16;
            #pragma unroll 4
            for (int j = i + 1; j < F; j++, dst += 16) {
                const float4 c = xv[j * 16 + q];
                float4 r;
                r.x = a.x*c.x; r.y = a.y*c.y; r.z = a.z*c.z; r.w = a.w*c.w;
                *dst = r;
            }
        }
        // Run 2: i = 30 - w2 (length 1 + w2); skip for w2 == 15 (duplicate of run 1)
        if (w2 < 15) {
            const int i = 30 - w2;
            const float4 a = xwv[i * 16 + q];
            float4* dst = og + (size_t)(i * 31 - i * (i - 1) / 2) * 16;
            #pragma unroll 4
            for (int j = i + 1; j < F; j++, dst += 16) {
                const float4 c = xv[j * 16 + q];
                float4 r;
                r.x = a.x*c.x; r.y = a.y*c.y; r.z = a.z*c.z; r.w = a.w*c.w;
                *dst = r;
            }
        }
    }
}

extern "C" void kernel_launch(void* const* d_in, const int* in_sizes, int n_in,
                              void* d_out, int out_size)
{
    // Robust input-order detection: W has exactly E*E elements, x is much larger.
    const float* x;
    const float* W;
    int x_elems;
    if (n_in >= 2 && in_sizes[0] > in_sizes[1]) {
        x = (const float*)d_in[0]; W = (const float*)d_in[1]; x_elems = in_sizes[0];
    } else {
        x = (const float*)d_in[1]; W = (const float*)d_in[0]; x_elems = in_sizes[1];
    }

    float* out = (float*)d_out;               // [B, P, E]
    const int B = x_elems / (F * E);          // 8192
    bilinear_kernel<<<B, THREADS>>>(x, W, out);
}

// round 16
// speedup vs baseline: 1.0828x; 1.0188x over previous
#include <cuda_runtime.h>

// BilinearInteractionLayer: out[b, p, e] = (x[b,i(p)] @ W)[e] * x[b,j(p)][e]
// B=8192, F=32, E=64, P=496. HBM-store-bound (~1.047 GB out, traffic-minimal).
//
// R9 = R8 (overlaid smem, float4 GEMM loads, run-structured store) plus:
//   - streaming stores (st.global.cs): output is write-once, evict-first in L2
//   - __launch_bounds__(256, 5): cap regs ~51 (was 53 -> 4 CTAs/SM reg-limited)

constexpr int F = 32;
constexpr int E = 64;
constexpr int P = 496;
constexpr int THREADS = 256;

__global__ __launch_bounds__(THREADS, 5) void bilinear_kernel(
    const float* __restrict__ x,     // [B, F, E]
    const float* __restrict__ W,     // [E, E]
    float* __restrict__ out)         // [B, P, E]
{
    __shared__ float xs [F * E];     // 8 KB   raw x[b]
    __shared__ float uni[E * E];     // 16 KB  W during GEMM, then xw (first 8 KB)

    const int tid = threadIdx.x;
    const int b   = blockIdx.x;

    // ---- Stage x[b] and W into smem (vectorized, coalesced) ----
    {
        const float4* xg  = reinterpret_cast<const float4*>(x + (size_t)b * F * E);
        float4*       xs4 = reinterpret_cast<float4*>(xs);
        #pragma unroll
        for (int i = 0; i < (F * E / 4) / THREADS; i++)       // 2 iters
            xs4[tid + i * THREADS] = xg[tid + i * THREADS];

        const float4* wg  = reinterpret_cast<const float4*>(W);
        float4*       un4 = reinterpret_cast<float4*>(uni);
        #pragma unroll
        for (int i = 0; i < (E * E / 4) / THREADS; i++)       // 4 iters
            un4[tid + i * THREADS] = wg[tid + i * THREADS];
    }
    __syncthreads();

    // ---- GEMM: xw = xs @ W. 128 threads, 4 rows x 4 cols each, accs in regs. ----
    float4 acc0 = {0.f,0.f,0.f,0.f};
    float4 acc1 = {0.f,0.f,0.f,0.f};
    float4 acc2 = {0.f,0.f,0.f,0.f};
    float4 acc3 = {0.f,0.f,0.f,0.f};
    const int q = tid & 15;
    const int w = tid >> 4;
    if (tid < 128) {
        const float4* Wv  = reinterpret_cast<const float4*>(uni);
        const float4* xsv = reinterpret_cast<const float4*>(xs);
        #pragma unroll
        for (int k4 = 0; k4 < E / 4; k4++) {
            const float4 a0v = xsv[(w     ) * 16 + k4];
            const float4 a1v = xsv[(w +  8) * 16 + k4];
            const float4 a2v = xsv[(w + 16) * 16 + k4];
            const float4 a3v = xsv[(w + 24) * 16 + k4];
            const float* a0p = &a0v.x;
            const float* a1p = &a1v.x;
            const float* a2p = &a2v.x;
            const float* a3p = &a3v.x;
            #pragma unroll
            for (int kk = 0; kk < 4; kk++) {
                const float4 wv = Wv[(k4 * 4 + kk) * 16 + q];
                const float a0 = a0p[kk], a1 = a1p[kk], a2 = a2p[kk], a3 = a3p[kk];
                acc0.x += a0*wv.x; acc0.y += a0*wv.y; acc0.z += a0*wv.z; acc0.w += a0*wv.w;
                acc1.x += a1*wv.x; acc1.y += a1*wv.y; acc1.z += a1*wv.z; acc1.w += a1*wv.w;
                acc2.x += a2*wv.x; acc2.y += a2*wv.y; acc2.z += a2*wv.z; acc2.w += a2*wv.w;
                acc3.x += a3*wv.x; acc3.y += a3*wv.y; acc3.z += a3*wv.z; acc3.w += a3*wv.w;
            }
        }
    }
    __syncthreads();                 // all W reads done; uni may be overwritten

    if (tid < 128) {
        float4* xwv = reinterpret_cast<float4*>(uni);     // overlay: xw in uni
        xwv[(w     ) * 16 + q] = acc0;
        xwv[(w +  8) * 16 + q] = acc1;
        xwv[(w + 16) * 16 + q] = acc2;
        xwv[(w + 24) * 16 + q] = acc3;
    }
    __syncthreads();

    // ---- Store: worker w2 owns runs i=w2 and i=30-w2; p0(i) = 31i - i(i-1)/2. ----
    // a = xw[i] register-cached per run; per row: 1 LDS.128 + 1 STG.128 (streaming).
    {
        const int w2 = tid >> 4;         // 0..15
        const float4* xwv = reinterpret_cast<const float4*>(uni);
        const float4* xv  = reinterpret_cast<const float4*>(xs);
        float4* og = reinterpret_cast<float4*>(out + (size_t)b * P * E) + q;

        // Run 1: i = w2 (length 31 - w2)
        {
            const int i = w2;
            const float4 a = xwv[i * 16 + q];
            float4* dst = og + (size_t)(i * 31 - i * (i - 1) / 2) * 16;
            #pragma unroll 4
            for (int j = i + 1; j < F; j++, dst += 16) {
                const float4 c = xv[j * 16 + q];
                float4 r;
                r.x = a.x*c.x; r.y = a.y*c.y; r.z = a.z*c.z; r.w = a.w*c.w;
                __stcs(dst, r);          // st.global.cs.v4 — evict-first streaming
            }
        }
        // Run 2: i = 30 - w2 (length 1 + w2); skip for w2 == 15 (duplicate of run 1)
        if (w2 < 15) {
            const int i = 30 - w2;
            const float4 a = xwv[i * 16 + q];
            float4* dst = og + (size_t)(i * 31 - i * (i - 1) / 2) * 16;
            #pragma unroll 4
            for (int j = i + 1; j < F; j++, dst += 16) {
                const float4 c = xv[j * 16 + q];
                float4 r;
                r.x = a.x*c.x; r.y = a.y*c.y; r.z = a.z*c.z; r.w = a.w*c.w;
                __stcs(dst, r);
            }
        }
    }
}

extern "C" void kernel_launch(void* const* d_in, const int* in_sizes, int n_in,
                              void* d_out, int out_size)
{
    // Robust input-order detection: W has exactly E*E elements, x is much larger.
    const float* x;
    const float* W;
    int x_elems;
    if (n_in >= 2 && in_sizes[0] > in_sizes[1]) {
        x = (const float*)d_in[0]; W = (const float*)d_in[1]; x_elems = in_sizes[0];
    } else {
        x = (const float*)d_in[1]; W = (const float*)d_in[0]; x_elems = in_sizes[1];
    }

    float* out = (float*)d_out;               // [B, P, E]
    const int B = x_elems / (F * E);          // 8192
    bilinear_kernel<<<B, THREADS>>>(x, W, out);
}